// round 1
// baseline (speedup 1.0000x reference)
#include <cuda_runtime.h>

// DifferentiableNERF: B chains x (L-1)-step NeRF backbone build.
// Strategy: each residue step is a rigid transform acting on the previous
// triplet's frame => associative affine composition => segmented parallel scan.
// One warp per chain; lane k owns ceil((L-1)/32) contiguous steps.
// Pass 1: simulate segment from canonical init triplet, extract segment
//         transform H_k = F(T0)^-1 o F(E_k).
// Warp Kogge-Stone scan of affines -> exclusive prefix -> true start triplet.
// Pass 2: re-simulate segment from true start, write outputs.

namespace {

struct V3 { float x, y, z; };

__device__ __forceinline__ V3 vsub(V3 a, V3 b) { return {a.x - b.x, a.y - b.y, a.z - b.z}; }
__device__ __forceinline__ V3 vcross(V3 a, V3 b) {
    return { a.y * b.z - a.z * b.y,
             a.z * b.x - a.x * b.z,
             a.x * b.y - a.y * b.x };
}
__device__ __forceinline__ float vdot(V3 a, V3 b) { return a.x * b.x + a.y * b.y + a.z * b.z; }
__device__ __forceinline__ V3 vunit(V3 a) {
    float r = rsqrtf(fmaxf(vdot(a, a), 1e-30f));
    return { a.x * r, a.y * r, a.z * r };
}

// Affine rigid transform: y = M x + t, m row-major 3x3.
struct Aff { float m[9]; float t[3]; };

__device__ __forceinline__ Aff identityAff() {
    Aff r;
    r.m[0] = 1.f; r.m[1] = 0.f; r.m[2] = 0.f;
    r.m[3] = 0.f; r.m[4] = 1.f; r.m[5] = 0.f;
    r.m[6] = 0.f; r.m[7] = 0.f; r.m[8] = 1.f;
    r.t[0] = 0.f; r.t[1] = 0.f; r.t[2] = 0.f;
    return r;
}

// (A o B)(x) = A(B(x))
__device__ __forceinline__ Aff compose(const Aff& A, const Aff& B) {
    Aff r;
#pragma unroll
    for (int i = 0; i < 3; i++) {
#pragma unroll
        for (int j = 0; j < 3; j++) {
            r.m[3 * i + j] = A.m[3 * i + 0] * B.m[0 + j]
                           + A.m[3 * i + 1] * B.m[3 + j]
                           + A.m[3 * i + 2] * B.m[6 + j];
        }
        r.t[i] = A.m[3 * i + 0] * B.t[0]
               + A.m[3 * i + 1] * B.t[1]
               + A.m[3 * i + 2] * B.t[2] + A.t[i];
    }
    return r;
}

__device__ __forceinline__ V3 applyAff(const Aff& A, V3 p) {
    return { A.m[0] * p.x + A.m[1] * p.y + A.m[2] * p.z + A.t[0],
             A.m[3] * p.x + A.m[4] * p.y + A.m[5] * p.z + A.t[1],
             A.m[6] * p.x + A.m[7] * p.y + A.m[8] * p.z + A.t[2] };
}

// Orthonormal frame of a triplet, matching the placement convention:
// ex = unit(c-b), ez = unit(cross(b-a, ex)), ey = ez x ex, origin = c.
__device__ __forceinline__ Aff frameOf(V3 a, V3 b, V3 c) {
    V3 ex = vunit(vsub(c, b));
    V3 ez = vunit(vcross(vsub(b, a), ex));
    V3 ey = vcross(ez, ex);
    Aff F;
    F.m[0] = ex.x; F.m[1] = ey.x; F.m[2] = ez.x;
    F.m[3] = ex.y; F.m[4] = ey.y; F.m[5] = ez.y;
    F.m[6] = ex.z; F.m[7] = ey.z; F.m[8] = ez.z;
    F.t[0] = c.x;  F.t[1] = c.y;  F.t[2] = c.z;
    return F;
}

__device__ __forceinline__ Aff invRigid(const Aff& A) {
    Aff r;
    r.m[0] = A.m[0]; r.m[1] = A.m[3]; r.m[2] = A.m[6];
    r.m[3] = A.m[1]; r.m[4] = A.m[4]; r.m[5] = A.m[7];
    r.m[6] = A.m[2]; r.m[7] = A.m[5]; r.m[8] = A.m[8];
#pragma unroll
    for (int i = 0; i < 3; i++) {
        r.t[i] = -(r.m[3 * i + 0] * A.t[0] + r.m[3 * i + 1] * A.t[1] + r.m[3 * i + 2] * A.t[2]);
    }
    return r;
}

__device__ __forceinline__ V3 place(V3 a, V3 b, V3 c, float ang, float len, float tor) {
    V3 bc = vunit(vsub(c, b));
    V3 n  = vunit(vcross(vsub(b, a), bc));
    V3 nbc = vcross(n, bc);
    float st, ct;
    __sincosf(tor, &st, &ct);
    float sa, ca;
    __sincosf(ang, &sa, &ca);
    float d0 = -len * ca;
    float d1 = len * ct * sa;
    float d2 = len * st * sa;
    return { c.x + bc.x * d0 + nbc.x * d1 + n.x * d2,
             c.y + bc.y * d0 + nbc.y * d1 + n.y * d2,
             c.z + bc.z * d0 + nbc.z * d1 + n.z * d2 };
}

__device__ __forceinline__ void stepFn(V3& a, V3& b, V3& c,
                                       float psi_i, float omega_i, float phi_i,
                                       float len_cn, float len_nca, float len_cac,
                                       float ang_cacn, float ang_cnca, float ang_ncac) {
    V3 n  = place(a, b, c, ang_cacn, len_cn, psi_i);
    V3 ca = place(b, c, n, ang_cnca, len_nca, omega_i);
    V3 cc = place(c, n, ca, ang_ncac, len_cac, phi_i);
    a = n; b = ca; c = cc;
}

__device__ __forceinline__ Aff shflUpAff(const Aff& A, int delta) {
    Aff r;
#pragma unroll
    for (int k = 0; k < 9; k++) r.m[k] = __shfl_up_sync(0xffffffffu, A.m[k], delta);
#pragma unroll
    for (int k = 0; k < 3; k++) r.t[k] = __shfl_up_sync(0xffffffffu, A.t[k], delta);
    return r;
}

__global__ void nerf_kernel(const float* __restrict__ phi,
                            const float* __restrict__ psi,
                            const float* __restrict__ omega,
                            const float* __restrict__ bl,
                            const float* __restrict__ ba,
                            float* __restrict__ out,
                            int B, int L) {
    const int lane = threadIdx.x & 31;
    const int warp = threadIdx.x >> 5;
    const int chain = blockIdx.x * (blockDim.x >> 5) + warp;
    if (chain >= B) return;

    const int nstep = L - 1;
    const int S = (nstep + 31) / 32;
    const int base = lane * S;
    int cnt = nstep - base;
    if (cnt < 0) cnt = 0;
    if (cnt > S) cnt = S;

    const V3 A0 = {17.047f, 14.099f, 3.625f};
    const V3 B0 = {16.967f, 12.784f, 4.338f};
    const V3 C0 = {15.685f, 12.755f, 5.133f};

    const float* __restrict__ phiR = phi + (size_t)chain * L;
    const float* __restrict__ psiR = psi + (size_t)chain * L;
    const float* __restrict__ omgR = omega + (size_t)chain * L;
    const float* __restrict__ blR  = bl + (size_t)chain * L * 3;
    const float* __restrict__ baR  = ba + (size_t)chain * L * 3;

    // ---- Pass 1: simulate segment from the canonical init triplet ----
    V3 a = A0, b = B0, c = C0;
    for (int j = 0; j < cnt; j++) {
        int i = base + j;
        stepFn(a, b, c,
               psiR[i], omgR[i], phiR[i + 1],
               blR[3 * i + 2], blR[3 * i + 0], blR[3 * i + 1],
               baR[3 * i + 1], baR[3 * i + 2], baR[3 * i + 0]);
    }

    const Aff F0  = frameOf(A0, B0, C0);
    const Aff F0i = invRigid(F0);

    Aff H;
    if (cnt > 0) H = compose(F0i, frameOf(a, b, c));
    else         H = identityAff();

    // ---- Warp-wide inclusive Kogge-Stone scan of affines ----
    Aff P = H;
#pragma unroll
    for (int off = 1; off < 32; off <<= 1) {
        Aff prev = shflUpAff(P, off);
        Aff comb = compose(prev, P);
        if (lane >= off) P = comb;
    }
    // Exclusive prefix; lane 0 starts at identity (start frame = F0)
    Aff Pex = shflUpAff(P, 1);

    Aff Q;  // world frame at this lane's segment start
    if (lane == 0) Q = F0;
    else           Q = compose(F0, Pex);

    // Rigid motion taking canonical triplet to this lane's start triplet.
    Aff W = compose(Q, F0i);
    a = applyAff(W, A0);
    b = applyAff(W, B0);
    c = applyAff(W, C0);

    // ---- Pass 2: re-simulate and write outputs ----
    float* __restrict__ outC = out + (size_t)chain * (size_t)(3 * L) * 3;
    if (lane == 0) {
        outC[0] = A0.x; outC[1] = A0.y; outC[2] = A0.z;
        outC[3] = B0.x; outC[4] = B0.y; outC[5] = B0.z;
        outC[6] = C0.x; outC[7] = C0.y; outC[8] = C0.z;
    }
    for (int j = 0; j < cnt; j++) {
        int i = base + j;
        stepFn(a, b, c,
               psiR[i], omgR[i], phiR[i + 1],
               blR[3 * i + 2], blR[3 * i + 0], blR[3 * i + 1],
               baR[3 * i + 1], baR[3 * i + 2], baR[3 * i + 0]);
        float* o = outC + (size_t)(3 + 3 * i) * 3;
        o[0] = a.x; o[1] = a.y; o[2] = a.z;
        o[3] = b.x; o[4] = b.y; o[5] = b.z;
        o[6] = c.x; o[7] = c.y; o[8] = c.z;
    }
}

} // anonymous namespace

extern "C" void kernel_launch(void* const* d_in, const int* in_sizes, int n_in,
                              void* d_out, int out_size) {
    const float* phi   = (const float*)d_in[0];
    const float* psi   = (const float*)d_in[1];
    const float* omega = (const float*)d_in[2];
    const float* bl    = (const float*)d_in[3];
    const float* ba    = (const float*)d_in[4];

    const int L = 512;
    const int B = in_sizes[0] / L;

    const int warpsPerBlock = 8;
    dim3 block(warpsPerBlock * 32);
    dim3 grid((B + warpsPerBlock - 1) / warpsPerBlock);
    nerf_kernel<<<grid, block>>>(phi, psi, omega, bl, ba, (float*)d_out, B, L);
}

// round 2
// speedup vs baseline: 2.6664x; 2.6664x over previous
#include <cuda_runtime.h>

// DifferentiableNERF, round 2.
// One warp per chain (B=4096, L=512). Lane k owns 16 contiguous steps.
// Pass 1: simulate segment from canonical init triplet (vectorized float4
//         input loads, fully unrolled), storing local positions in SMEM.
// Warp Kogge-Stone scan of segment rigid transforms -> per-lane world
//         transform W.
// Pass 2: apply W to the stored local trajectory in SMEM (no reloads,
//         no sincos), then warp-cooperative fully-coalesced writeout of the
//         chain's 4608 contiguous floats.

namespace {

constexpr int L_CONST = 512;
constexpr int NSTEP = L_CONST - 1;   // 511
constexpr int SEG = 16;              // steps per lane
constexpr int THREADS = 64;          // 2 warps / block
constexpr int CHAIN_FLOATS = 3 * L_CONST * 3;  // 4608

struct V3 { float x, y, z; };

__device__ __forceinline__ V3 vsub(V3 a, V3 b) { return {a.x - b.x, a.y - b.y, a.z - b.z}; }
__device__ __forceinline__ V3 vcross(V3 a, V3 b) {
    return { a.y * b.z - a.z * b.y,
             a.z * b.x - a.x * b.z,
             a.x * b.y - a.y * b.x };
}
__device__ __forceinline__ float vdot(V3 a, V3 b) { return a.x * b.x + a.y * b.y + a.z * b.z; }
__device__ __forceinline__ V3 vunit(V3 a) {
    float r = rsqrtf(fmaxf(vdot(a, a), 1e-30f));
    return { a.x * r, a.y * r, a.z * r };
}

struct Aff { float m[9]; float t[3]; };

// (A o B)(x) = A(B(x))
__device__ __forceinline__ Aff compose(const Aff& A, const Aff& B) {
    Aff r;
#pragma unroll
    for (int i = 0; i < 3; i++) {
#pragma unroll
        for (int j = 0; j < 3; j++) {
            r.m[3 * i + j] = A.m[3 * i + 0] * B.m[0 + j]
                           + A.m[3 * i + 1] * B.m[3 + j]
                           + A.m[3 * i + 2] * B.m[6 + j];
        }
        r.t[i] = A.m[3 * i + 0] * B.t[0]
               + A.m[3 * i + 1] * B.t[1]
               + A.m[3 * i + 2] * B.t[2] + A.t[i];
    }
    return r;
}

__device__ __forceinline__ V3 applyAff(const Aff& A, V3 p) {
    return { A.m[0] * p.x + A.m[1] * p.y + A.m[2] * p.z + A.t[0],
             A.m[3] * p.x + A.m[4] * p.y + A.m[5] * p.z + A.t[1],
             A.m[6] * p.x + A.m[7] * p.y + A.m[8] * p.z + A.t[2] };
}

// ex = unit(c-b), ez = unit(cross(b-a, ex)), ey = ez x ex, origin = c.
__device__ __forceinline__ Aff frameOf(V3 a, V3 b, V3 c) {
    V3 ex = vunit(vsub(c, b));
    V3 ez = vunit(vcross(vsub(b, a), ex));
    V3 ey = vcross(ez, ex);
    Aff F;
    F.m[0] = ex.x; F.m[1] = ey.x; F.m[2] = ez.x;
    F.m[3] = ex.y; F.m[4] = ey.y; F.m[5] = ez.y;
    F.m[6] = ex.z; F.m[7] = ey.z; F.m[8] = ez.z;
    F.t[0] = c.x;  F.t[1] = c.y;  F.t[2] = c.z;
    return F;
}

__device__ __forceinline__ Aff invRigid(const Aff& A) {
    Aff r;
    r.m[0] = A.m[0]; r.m[1] = A.m[3]; r.m[2] = A.m[6];
    r.m[3] = A.m[1]; r.m[4] = A.m[4]; r.m[5] = A.m[7];
    r.m[6] = A.m[2]; r.m[7] = A.m[5]; r.m[8] = A.m[8];
#pragma unroll
    for (int i = 0; i < 3; i++) {
        r.t[i] = -(r.m[3 * i + 0] * A.t[0] + r.m[3 * i + 1] * A.t[1] + r.m[3 * i + 2] * A.t[2]);
    }
    return r;
}

__device__ __forceinline__ V3 place(V3 a, V3 b, V3 c, float ang, float len, float tor) {
    V3 bc = vunit(vsub(c, b));
    V3 n  = vunit(vcross(vsub(b, a), bc));
    V3 nbc = vcross(n, bc);
    float st, ct;
    __sincosf(tor, &st, &ct);
    float sa, ca;
    __sincosf(ang, &sa, &ca);
    float d0 = -len * ca;
    float d1 = len * ct * sa;
    float d2 = len * st * sa;
    return { c.x + bc.x * d0 + nbc.x * d1 + n.x * d2,
             c.y + bc.y * d0 + nbc.y * d1 + n.y * d2,
             c.z + bc.z * d0 + nbc.z * d1 + n.z * d2 };
}

__device__ __forceinline__ void stepFn(V3& a, V3& b, V3& c,
                                       float psi_i, float omega_i, float phi_i,
                                       float len_cn, float len_nca, float len_cac,
                                       float ang_cacn, float ang_cnca, float ang_ncac) {
    V3 n  = place(a, b, c, ang_cacn, len_cn, psi_i);
    V3 ca = place(b, c, n, ang_cnca, len_nca, omega_i);
    V3 cc = place(c, n, ca, ang_ncac, len_cac, phi_i);
    a = n; b = ca; c = cc;
}

__device__ __forceinline__ Aff shflUpAff(const Aff& A, int delta) {
    Aff r;
#pragma unroll
    for (int k = 0; k < 9; k++) r.m[k] = __shfl_up_sync(0xffffffffu, A.m[k], delta);
#pragma unroll
    for (int k = 0; k < 3; k++) r.t[k] = __shfl_up_sync(0xffffffffu, A.t[k], delta);
    return r;
}

__device__ const float c9[9] = {
    17.047f, 14.099f, 3.625f,
    16.967f, 12.784f, 4.338f,
    15.685f, 12.755f, 5.133f
};

__global__ __launch_bounds__(THREADS)
void nerf_kernel(const float* __restrict__ phi,
                 const float* __restrict__ psi,
                 const float* __restrict__ omega,
                 const float* __restrict__ bl,
                 const float* __restrict__ ba,
                 float* __restrict__ out,
                 int B) {
    // Bank-conflict-free trajectory store: traj[k][tid], row stride 65.
    __shared__ float traj[SEG * 9][THREADS + 1];

    const int tid  = threadIdx.x;
    const int lane = tid & 31;
    const int warp = tid >> 5;
    const int wbase = warp << 5;
    const int chain = blockIdx.x * 2 + warp;
    if (chain >= B) return;

    const int base = lane * SEG;

    const V3 A0 = {17.047f, 14.099f, 3.625f};
    const V3 B0 = {16.967f, 12.784f, 4.338f};
    const V3 C0 = {15.685f, 12.755f, 5.133f};

    const float* __restrict__ phiR = phi   + (size_t)chain * L_CONST;
    const float* __restrict__ psiS = psi   + (size_t)chain * L_CONST + base;
    const float* __restrict__ omgS = omega + (size_t)chain * L_CONST + base;
    const float* __restrict__ blS  = bl + (size_t)chain * L_CONST * 3 + 3 * base;
    const float* __restrict__ baS  = ba + (size_t)chain * L_CONST * 3 + 3 * base;

    // ---- Pass 1: simulate segment from canonical init; record local traj ----
    V3 a = A0, b = B0, c = C0;
#pragma unroll
    for (int g = 0; g < 4; g++) {
        // Vectorized, front-batched input loads for 4 steps.
        float4 psq = *(const float4*)(psiS + 4 * g);
        float4 omq = *(const float4*)(omgS + 4 * g);
        float4 blq[3], baq[3];
#pragma unroll
        for (int q = 0; q < 3; q++) {
            blq[q] = *(const float4*)(blS + 12 * g + 4 * q);
            baq[q] = *(const float4*)(baS + 12 * g + 4 * q);
        }
        float phv[4];
#pragma unroll
        for (int t = 0; t < 4; t++) {
            int ip = base + 4 * g + t + 1;
            if (ip > NSTEP) ip = NSTEP;   // clamp (only lane 31, last step)
            phv[t] = phiR[ip];
        }
        const float* psf = (const float*)&psq;
        const float* omf = (const float*)&omq;
        const float* blf = (const float*)blq;
        const float* baf = (const float*)baq;
#pragma unroll
        for (int t = 0; t < 4; t++) {
            int i = base + 4 * g + t;
            if (i < NSTEP) {
                stepFn(a, b, c,
                       psf[t], omf[t], phv[t],
                       blf[3 * t + 2], blf[3 * t + 0], blf[3 * t + 1],
                       baf[3 * t + 1], baf[3 * t + 2], baf[3 * t + 0]);
                int s = 4 * g + t;
                traj[9 * s + 0][tid] = a.x; traj[9 * s + 1][tid] = a.y; traj[9 * s + 2][tid] = a.z;
                traj[9 * s + 3][tid] = b.x; traj[9 * s + 4][tid] = b.y; traj[9 * s + 5][tid] = b.z;
                traj[9 * s + 6][tid] = c.x; traj[9 * s + 7][tid] = c.y; traj[9 * s + 8][tid] = c.z;
            }
        }
    }

    // ---- Segment transform + warp Kogge-Stone scan ----
    const Aff F0  = frameOf(A0, B0, C0);
    const Aff F0i = invRigid(F0);
    Aff P = compose(F0i, frameOf(a, b, c));   // every lane has >=15 steps

#pragma unroll
    for (int off = 1; off < 32; off <<= 1) {
        Aff prev = shflUpAff(P, off);
        Aff comb = compose(prev, P);
        if (lane >= off) P = comb;
    }
    Aff Pex = shflUpAff(P, 1);   // exclusive prefix

    Aff Q;   // world frame at this lane's segment start
    if (lane == 0) Q = F0;
    else           Q = compose(F0, Pex);
    const Aff W = compose(Q, F0i);   // canonical coords -> world coords

    // ---- Pass 2: transform local trajectory in SMEM ----
#pragma unroll
    for (int s = 0; s < SEG; s++) {
#pragma unroll
        for (int p = 0; p < 3; p++) {
            V3 v;
            v.x = traj[9 * s + 3 * p + 0][tid];
            v.y = traj[9 * s + 3 * p + 1][tid];
            v.z = traj[9 * s + 3 * p + 2][tid];
            V3 w = applyAff(W, v);
            traj[9 * s + 3 * p + 0][tid] = w.x;
            traj[9 * s + 3 * p + 1][tid] = w.y;
            traj[9 * s + 3 * p + 2][tid] = w.z;
        }
    }
    __syncwarp();

    // ---- Coalesced cooperative writeout: 4608 contiguous floats/chain ----
    float* __restrict__ outC = out + (size_t)chain * CHAIN_FLOATS;

    // First 32 elements: indices 0..8 are the init triplet constants.
    {
        float v;
        if (lane < 9) v = c9[lane];
        else          v = traj[lane - 9][wbase];   // owner lane 0, k = lane-9
        outC[lane] = v;
    }
    int idx = lane + 32;
    int k = lane + 23;   // (idx - 9) % 144 for owner 0
    int owner = 0;
    for (int it = 1; it < CHAIN_FLOATS / 32; it++) {
        outC[idx] = traj[k][wbase + owner];
        idx += 32;
        k += 32;
        if (k >= SEG * 9) { k -= SEG * 9; owner++; }
    }
}

} // anonymous namespace

extern "C" void kernel_launch(void* const* d_in, const int* in_sizes, int n_in,
                              void* d_out, int out_size) {
    const float* phi   = (const float*)d_in[0];
    const float* psi   = (const float*)d_in[1];
    const float* omega = (const float*)d_in[2];
    const float* bl    = (const float*)d_in[3];
    const float* ba    = (const float*)d_in[4];

    const int B = in_sizes[0] / L_CONST;

    dim3 block(THREADS);
    dim3 grid((B + 1) / 2);
    nerf_kernel<<<grid, block>>>(phi, psi, omega, bl, ba, (float*)d_out, B);
}

// round 3
// speedup vs baseline: 4.8103x; 1.8041x over previous
#include <cuda_runtime.h>

// DifferentiableNERF, round 3.
// One BLOCK (128 threads, 4 warps) per chain; thread owns SEG=4 steps.
// Pass 1: simulate 4 steps from canonical init triplet, record local
//         positions in block SMEM.
// Conjugated-space scan: H' = F(endpoint) o F0^-1; warp Kogge-Stone scan
//         + 4-way cross-warp combine => exclusive prefix = W directly.
// Pass 2: apply W in-place in SMEM, then block-cooperative fully-coalesced
//         writeout of the chain's 4608 contiguous floats.

namespace {

constexpr int L_CONST = 512;
constexpr int NSTEP = L_CONST - 1;   // 511
constexpr int SEG = 4;               // steps per thread
constexpr int THREADS = 128;         // 4 warps = 1 chain
constexpr int CHAIN_FLOATS = 3 * L_CONST * 3;  // 4608
constexpr int ROWS = SEG * 9;        // 36

struct V3 { float x, y, z; };

__device__ __forceinline__ V3 vsub(V3 a, V3 b) { return {a.x - b.x, a.y - b.y, a.z - b.z}; }
__device__ __forceinline__ V3 vcross(V3 a, V3 b) {
    return { a.y * b.z - a.z * b.y,
             a.z * b.x - a.x * b.z,
             a.x * b.y - a.y * b.x };
}
__device__ __forceinline__ float vdot(V3 a, V3 b) { return a.x * b.x + a.y * b.y + a.z * b.z; }
__device__ __forceinline__ V3 vunit(V3 a) {
    float r = rsqrtf(fmaxf(vdot(a, a), 1e-30f));
    return { a.x * r, a.y * r, a.z * r };
}

struct Aff { float m[9]; float t[3]; };

__device__ __forceinline__ Aff identityAff() {
    Aff r;
    r.m[0] = 1.f; r.m[1] = 0.f; r.m[2] = 0.f;
    r.m[3] = 0.f; r.m[4] = 1.f; r.m[5] = 0.f;
    r.m[6] = 0.f; r.m[7] = 0.f; r.m[8] = 1.f;
    r.t[0] = 0.f; r.t[1] = 0.f; r.t[2] = 0.f;
    return r;
}

// (A o B)(x) = A(B(x))
__device__ __forceinline__ Aff compose(const Aff& A, const Aff& B) {
    Aff r;
#pragma unroll
    for (int i = 0; i < 3; i++) {
#pragma unroll
        for (int j = 0; j < 3; j++) {
            r.m[3 * i + j] = A.m[3 * i + 0] * B.m[0 + j]
                           + A.m[3 * i + 1] * B.m[3 + j]
                           + A.m[3 * i + 2] * B.m[6 + j];
        }
        r.t[i] = A.m[3 * i + 0] * B.t[0]
               + A.m[3 * i + 1] * B.t[1]
               + A.m[3 * i + 2] * B.t[2] + A.t[i];
    }
    return r;
}

__device__ __forceinline__ V3 applyAff(const Aff& A, V3 p) {
    return { A.m[0] * p.x + A.m[1] * p.y + A.m[2] * p.z + A.t[0],
             A.m[3] * p.x + A.m[4] * p.y + A.m[5] * p.z + A.t[1],
             A.m[6] * p.x + A.m[7] * p.y + A.m[8] * p.z + A.t[2] };
}

// ex = unit(c-b), ez = unit(cross(b-a, ex)), ey = ez x ex, origin = c.
__device__ __forceinline__ Aff frameOf(V3 a, V3 b, V3 c) {
    V3 ex = vunit(vsub(c, b));
    V3 ez = vunit(vcross(vsub(b, a), ex));
    V3 ey = vcross(ez, ex);
    Aff F;
    F.m[0] = ex.x; F.m[1] = ey.x; F.m[2] = ez.x;
    F.m[3] = ex.y; F.m[4] = ey.y; F.m[5] = ez.y;
    F.m[6] = ex.z; F.m[7] = ey.z; F.m[8] = ez.z;
    F.t[0] = c.x;  F.t[1] = c.y;  F.t[2] = c.z;
    return F;
}

__device__ __forceinline__ Aff invRigid(const Aff& A) {
    Aff r;
    r.m[0] = A.m[0]; r.m[1] = A.m[3]; r.m[2] = A.m[6];
    r.m[3] = A.m[1]; r.m[4] = A.m[4]; r.m[5] = A.m[7];
    r.m[6] = A.m[2]; r.m[7] = A.m[5]; r.m[8] = A.m[8];
#pragma unroll
    for (int i = 0; i < 3; i++) {
        r.t[i] = -(r.m[3 * i + 0] * A.t[0] + r.m[3 * i + 1] * A.t[1] + r.m[3 * i + 2] * A.t[2]);
    }
    return r;
}

__device__ __forceinline__ V3 place(V3 a, V3 b, V3 c, float ang, float len, float tor) {
    V3 bc = vunit(vsub(c, b));
    V3 n  = vunit(vcross(vsub(b, a), bc));
    V3 nbc = vcross(n, bc);
    float st, ct;
    __sincosf(tor, &st, &ct);
    float sa, ca;
    __sincosf(ang, &sa, &ca);
    float d0 = -len * ca;
    float d1 = len * ct * sa;
    float d2 = len * st * sa;
    return { c.x + bc.x * d0 + nbc.x * d1 + n.x * d2,
             c.y + bc.y * d0 + nbc.y * d1 + n.y * d2,
             c.z + bc.z * d0 + nbc.z * d1 + n.z * d2 };
}

__device__ __forceinline__ void stepFn(V3& a, V3& b, V3& c,
                                       float psi_i, float omega_i, float phi_i,
                                       float len_cn, float len_nca, float len_cac,
                                       float ang_cacn, float ang_cnca, float ang_ncac) {
    V3 n  = place(a, b, c, ang_cacn, len_cn, psi_i);
    V3 ca = place(b, c, n, ang_cnca, len_nca, omega_i);
    V3 cc = place(c, n, ca, ang_ncac, len_cac, phi_i);
    a = n; b = ca; c = cc;
}

__device__ __forceinline__ Aff shflUpAff(const Aff& A, int delta) {
    Aff r;
#pragma unroll
    for (int k = 0; k < 9; k++) r.m[k] = __shfl_up_sync(0xffffffffu, A.m[k], delta);
#pragma unroll
    for (int k = 0; k < 3; k++) r.t[k] = __shfl_up_sync(0xffffffffu, A.t[k], delta);
    return r;
}

__constant__ float c9[9] = {
    17.047f, 14.099f, 3.625f,
    16.967f, 12.784f, 4.338f,
    15.685f, 12.755f, 5.133f
};

__global__ __launch_bounds__(THREADS, 5)
void nerf_kernel(const float* __restrict__ phi,
                 const float* __restrict__ psi,
                 const float* __restrict__ omega,
                 const float* __restrict__ bl,
                 const float* __restrict__ ba,
                 float* __restrict__ out) {
    __shared__ float traj[ROWS][THREADS + 1];
    __shared__ float warpTot[3][12];   // inclusive totals of warps 0..2

    const int tid  = threadIdx.x;
    const int lane = tid & 31;
    const int warp = tid >> 5;
    const int chain = blockIdx.x;

    const int base = tid * SEG;

    const V3 A0 = {17.047f, 14.099f, 3.625f};
    const V3 B0 = {16.967f, 12.784f, 4.338f};
    const V3 C0 = {15.685f, 12.755f, 5.133f};

    const float* __restrict__ phiR = phi   + (size_t)chain * L_CONST;
    const float* __restrict__ psiS = psi   + (size_t)chain * L_CONST + base;
    const float* __restrict__ omgS = omega + (size_t)chain * L_CONST + base;
    const float* __restrict__ blS  = bl + (size_t)chain * L_CONST * 3 + 3 * base;
    const float* __restrict__ baS  = ba + (size_t)chain * L_CONST * 3 + 3 * base;

    // ---- Batched vector loads of this thread's 4-step inputs ----
    float4 psq = *(const float4*)psiS;
    float4 omq = *(const float4*)omgS;
    float4 blq[3], baq[3];
#pragma unroll
    for (int q = 0; q < 3; q++) {
        blq[q] = *(const float4*)(blS + 4 * q);
        baq[q] = *(const float4*)(baS + 4 * q);
    }
    float4 phq = *(const float4*)(phiR + base);   // phi[base .. base+3]
    // Need phi[base+1 .. base+4]; last one from the neighbor lane (or scalar).
    float ph3 = __shfl_down_sync(0xffffffffu, phq.x, 1);
    if (lane == 31) {
        int ip = base + SEG;
        ph3 = (ip < L_CONST) ? phiR[ip] : 0.f;
    }
    float phv[4] = { phq.y, phq.z, phq.w, ph3 };
    const float* psf = (const float*)&psq;
    const float* omf = (const float*)&omq;
    const float* blf = (const float*)blq;
    const float* baf = (const float*)baq;

    // ---- Pass 1: simulate segment from canonical init; record local traj ----
    V3 a = A0, b = B0, c = C0;
#pragma unroll
    for (int t = 0; t < SEG; t++) {
        int i = base + t;
        if (i < NSTEP) {
            stepFn(a, b, c,
                   psf[t], omf[t], phv[t],
                   blf[3 * t + 2], blf[3 * t + 0], blf[3 * t + 1],
                   baf[3 * t + 1], baf[3 * t + 2], baf[3 * t + 0]);
            traj[9 * t + 0][tid] = a.x; traj[9 * t + 1][tid] = a.y; traj[9 * t + 2][tid] = a.z;
            traj[9 * t + 3][tid] = b.x; traj[9 * t + 4][tid] = b.y; traj[9 * t + 5][tid] = b.z;
            traj[9 * t + 6][tid] = c.x; traj[9 * t + 7][tid] = c.y; traj[9 * t + 8][tid] = c.z;
        }
    }

    // ---- Conjugated segment transform: H' = F(end) o F0^-1 ----
    const Aff F0i = invRigid(frameOf(A0, B0, C0));
    Aff P = compose(frameOf(a, b, c), F0i);

    // Warp inclusive Kogge-Stone scan
#pragma unroll
    for (int off = 1; off < 32; off <<= 1) {
        Aff prev = shflUpAff(P, off);
        Aff comb = compose(prev, P);
        if (lane >= off) P = comb;
    }

    // Publish warp totals
    if (lane == 31 && warp < 3) {
#pragma unroll
        for (int k = 0; k < 9; k++) warpTot[warp][k] = P.m[k];
#pragma unroll
        for (int k = 0; k < 3; k++) warpTot[warp][9 + k] = P.t[k];
    }

    Aff Pex = shflUpAff(P, 1);   // warp-local exclusive prefix
    __syncthreads();

    // W = warpTot[0] o ... o warpTot[warp-1] o Pex   (exclusive prefix = W)
    Aff W = (lane == 0) ? identityAff() : Pex;
    for (int v = warp - 1; v >= 0; v--) {
        Aff T;
#pragma unroll
        for (int k = 0; k < 9; k++) T.m[k] = warpTot[v][k];
#pragma unroll
        for (int k = 0; k < 3; k++) T.t[k] = warpTot[v][9 + k];
        W = compose(T, W);
    }

    // ---- Pass 2: transform local trajectory in SMEM ----
#pragma unroll
    for (int s = 0; s < SEG; s++) {
#pragma unroll
        for (int p = 0; p < 3; p++) {
            V3 v;
            v.x = traj[9 * s + 3 * p + 0][tid];
            v.y = traj[9 * s + 3 * p + 1][tid];
            v.z = traj[9 * s + 3 * p + 2][tid];
            V3 w = applyAff(W, v);
            traj[9 * s + 3 * p + 0][tid] = w.x;
            traj[9 * s + 3 * p + 1][tid] = w.y;
            traj[9 * s + 3 * p + 2][tid] = w.z;
        }
    }
    __syncthreads();

    // ---- Coalesced cooperative writeout: 4608 contiguous floats/chain ----
    float* __restrict__ outC = out + (size_t)chain * CHAIN_FLOATS;
#pragma unroll
    for (int it = 0; it < CHAIN_FLOATS / THREADS; it++) {
        int f = it * THREADS + tid;
        float v;
        if (f < 9) {
            v = c9[f];
        } else {
            int g = f - 9;
            int i = g / 9;            // global step index
            int owner = i >> 2;       // owning thread (SEG=4)
            int row = g - ROWS * owner;
            v = traj[row][owner];
        }
        outC[f] = v;
    }
}

} // anonymous namespace

extern "C" void kernel_launch(void* const* d_in, const int* in_sizes, int n_in,
                              void* d_out, int out_size) {
    const float* phi   = (const float*)d_in[0];
    const float* psi   = (const float*)d_in[1];
    const float* omega = (const float*)d_in[2];
    const float* bl    = (const float*)d_in[3];
    const float* ba    = (const float*)d_in[4];

    const int B = in_sizes[0] / L_CONST;

    nerf_kernel<<<B, THREADS>>>(phi, psi, omega, bl, ba, (float*)d_out);
}